// round 13
// baseline (speedup 1.0000x reference)
#include <cuda_runtime.h>
#include <cuda_bf16.h>
#include <cstdint>

// Problem shapes (fixed for this dataset entry)
constexpr int B = 4;
constexpr int S = 4096;
constexpr int D = 2048;
constexpr int HALO   = 8;
constexpr int NROWS  = 2048;
constexpr int NTOK   = B * S;             // 16384
constexpr int CHUNK  = 16;
constexpr int NCHUNK = NTOK / CHUNK;      // 1024

constexpr int PRE_BLOCKS  = 86;           // co-resident (< 148 SMs) => spin-safe
constexpr int PRE_THREADS = 256;          // 8 warps; warp covers 24 tokens

// Device scratch (no allocs allowed)
__device__ float    g_w[NTOK * HALO];
__device__ unsigned g_flag[NTOK];
__device__ int      g_cnt[NROWS];         // zeroed at end of each pre launch
__device__ int      g_cur[NROWS];
__device__ int      g_order[NTOK];
__device__ int      g_bar[2];             // monotonic barrier counters
__device__ int      g_epoch;              // completed-launch count

// Grid barrier: monotonic counter, target = (epoch+1)*PRE_BLOCKS.
__device__ __forceinline__ void gbar(int i, int E, bool bump_epoch)
{
    __syncthreads();
    if (threadIdx.x == 0) {
        const int tgt = (E + 1) * PRE_BLOCKS;
        __threadfence();
        const int old = atomicAdd(&g_bar[i], 1);
        if (bump_epoch && old == tgt - 1)
            atomicExch(&g_epoch, E + 1);
        while (atomicAdd(&g_bar[i], 0) < tgt) { }
        __threadfence();
    }
    __syncthreads();
}

// ---------------------------------------------------------------------------
// Pre-kernel: weight DP + histogram -> bar -> scan (block 0) -> bar ->
//             scatter + zero g_cnt.  One launch, ~3 us.
//  DP (per warp, lane = token): w^k[j] = w^{k-1}[j] + p[t-k] * w^{k-1}_nb[j-1],
//  w_0 == 1 implicit; influence moves 1 lane/level => lanes >= 8 exact.
//  p[s] valid only within the token's own batch (boundary zero-fill).
// ---------------------------------------------------------------------------
__global__ __launch_bounds__(PRE_THREADS)
void pre_kernel(const int* __restrict__ x)
{
    const int tid  = threadIdx.x;
    const int wid  = tid >> 5;
    const int lane = tid & 31;

    __shared__ int sE;
    __shared__ int wsums[8];

    if (tid == 0) sE = *(volatile int*)&g_epoch;
    __syncthreads();
    const int E = sE;

    // ---- Phase A: DP + hist ----
    const int W  = blockIdx.x * 8 + wid;          // global warp id
    const int tf = W * 24 - 8 + lane;             // token (lane<8: halo)
    const bool valid = (lane >= HALO) && (tf >= 0) && (tf < NTOK);

    int xs[9];
#pragma unroll
    for (int i = 0; i < 9; i++) {
        int s = tf - 8 + i;
        s = max(0, min(s, NTOK - 1));
        xs[i] = x[s];
    }
    const int xv = xs[8];                          // x[tf] (clamped for halo)

    unsigned pm = 0;
    if (tf >= 0 && tf < NTOK) {
        const int bstart = tf & ~(S - 1);          // batch start (linear)
#pragma unroll
        for (int k = 1; k <= 8; k++) {
            const int s = tf - k;
            if (s >= bstart && xs[8 - k] >= 16 && xs[9 - k] < 16)
                pm |= (1u << k);
        }
    }

    float wj[HALO];
#pragma unroll
    for (int j = 0; j < HALO; j++) wj[j] = 0.0f;
#pragma unroll
    for (int k = 1; k <= 8; k++) {
        const float pv = (pm >> k) & 1u ? 1.0f : 0.0f;
        float nb[HALO - 1];
#pragma unroll
        for (int j = 0; j < HALO - 1; j++)
            nb[j] = __shfl_up_sync(0xFFFFFFFFu, wj[j], 1);
        float nb0 = 1.0f;
        if (lane == 0) {
            nb0 = 0.0f;
#pragma unroll
            for (int j = 0; j < HALO - 1; j++) nb[j] = 0.0f;
        }
        wj[0] = fmaf(pv, nb0, wj[0]);
#pragma unroll
        for (int j = 1; j < HALO; j++) wj[j] = fmaf(pv, nb[j - 1], wj[j]);
    }

    if (valid) {
        unsigned m = 0;
#pragma unroll
        for (int j = 0; j < HALO; j++) {
            if (wj[j] != 0.0f) m |= (1u << (j + 1));
            g_w[(size_t)tf * HALO + j] = wj[j];
        }
        g_flag[tf] = m;
        atomicAdd(&g_cnt[xv], 1);
    }

    gbar(0, E, false);

    // ---- Phase B: block 0 scans g_cnt -> g_cur (exclusive offsets) ----
    if (blockIdx.x == 0) {
        const int base = tid * 8;
        int v[8], pre[8];
        int run = 0;
#pragma unroll
        for (int j = 0; j < 8; j++) {
            v[j]  = g_cnt[base + j];
            pre[j] = run;
            run  += v[j];
        }
        int incl = run;
#pragma unroll
        for (int off = 1; off < 32; off <<= 1) {
            const int n = __shfl_up_sync(0xFFFFFFFFu, incl, off);
            if (lane >= off) incl += n;
        }
        if (lane == 31) wsums[wid] = incl;
        __syncthreads();
        if (wid == 0) {
            int wv = (lane < 8) ? wsums[lane] : 0;
            int wincl = wv;
#pragma unroll
            for (int off = 1; off < 8; off <<= 1) {
                const int n = __shfl_up_sync(0xFFFFFFFFu, wincl, off);
                if (lane >= off) wincl += n;
            }
            if (lane < 8) wsums[lane] = wincl - wv;   // exclusive warp base
        }
        __syncthreads();
        const int tbase = wsums[wid] + (incl - run);
#pragma unroll
        for (int j = 0; j < 8; j++)
            g_cur[base + j] = tbase + pre[j];
    }

    gbar(1, E, true);   // last arriver bumps epoch

    // ---- Phase C: scatter + zero g_cnt for next launch ----
    if (valid) {
        const int pos = atomicAdd(&g_cur[xv], 1);
        g_order[pos] = tf;
    }
    const int gi = blockIdx.x * PRE_THREADS + tid;
    if (gi < NROWS) g_cnt[gi] = 0;
}

// ---------------------------------------------------------------------------
// Output kernel: block = 16 row-grouped tokens; row in registers, reloaded on
// (block-uniform) row change with one-segment-ahead prefetch. Slow tokens
// (flag != 0) corrected inline: out[t] = e[x[t]] + sum_j w_j(t) * e[x[t-j]].
// Correctness does not depend on g_order's ordering.
// ---------------------------------------------------------------------------
__global__ __launch_bounds__(512)
void out_kernel(const int* __restrict__ x,
                const float* __restrict__ emb,
                float* __restrict__ out)
{
    const int tid = threadIdx.x;
    const int c0  = blockIdx.x * CHUNK;

    __shared__ int      socc[CHUNK];
    __shared__ int      srow[CHUNK];
    __shared__ unsigned sfl[CHUNK];

    if (tid < CHUNK) {
        const int idx = g_order[c0 + tid];
        socc[tid] = idx;
        srow[tid] = __ldg(&x[idx]);
        sfl[tid]  = g_flag[idx];
    }
    __syncthreads();

    int    r     = srow[0];
    float4 e_cur = *reinterpret_cast<const float4*>(emb + (size_t)r * D + tid * 4);

    int k = 0;
    while (k < CHUNK) {
        int kend = k + 1;
        while (kend < CHUNK && srow[kend] == r) kend++;

        // prefetch next segment's row before draining this segment's stores
        float4 e_next = e_cur;
        int    rnext  = r;
        if (kend < CHUNK) {
            rnext  = srow[kend];
            e_next = *reinterpret_cast<const float4*>(
                emb + (size_t)rnext * D + tid * 4);
        }

        for (; k < kend; k++) {
            float4 c = e_cur;
            const unsigned m = sfl[k];
            if (m) {
                const int tf = socc[k];
#pragma unroll
                for (int j = 1; j <= HALO; j++) {
                    if ((m >> j) & 1u) {
                        // bit j set => w_j != 0 => t-j stays inside this sequence
                        const float  w  = __ldg(&g_w[(size_t)tf * HALO + (j - 1)]);
                        const int    rj = __ldg(&x[tf - j]);
                        const float4 h  = *reinterpret_cast<const float4*>(
                            emb + (size_t)rj * D + tid * 4);
                        c.x = fmaf(h.x, w, c.x);
                        c.y = fmaf(h.y, w, c.y);
                        c.z = fmaf(h.z, w, c.z);
                        c.w = fmaf(h.w, w, c.w);
                    }
                }
            }
            __stcs(reinterpret_cast<float4*>(out + (size_t)socc[k] * D + tid * 4), c);
        }
        r     = rnext;
        e_cur = e_next;
    }
}

extern "C" void kernel_launch(void* const* d_in, const int* in_sizes, int n_in,
                              void* d_out, int out_size)
{
    const int*   x   = (const int*)d_in[0];
    const float* emb = (const float*)d_in[1];
    float*       out = (float*)d_out;

    pre_kernel<<<PRE_BLOCKS, PRE_THREADS>>>(x);
    out_kernel<<<NCHUNK, 512>>>(x, emb, out);
}